// round 6
// baseline (speedup 1.0000x reference)
#include <cuda_runtime.h>

// ChamferDistance_755914244601: B=4, N=M=8192, 3D points.
// Fused single pass: each block computes a 256-col x 512-row stripe of the
// distance matrix once, row mins + col mins together. Packed f32x2 FFMA2/FADD2
// for the distance chain, scalar FMNMX for mins (2/pair, mandatory).
// 2048 blocks -> ~7 waves at occ 2 => ~1% wave-tail waste.

#define BB 4
#define NN 8192
#define MM 8192
#define BC 256          // cols per block
#define KC 8            // cols per lane
#define NCP (KC / 2)    // colpairs per lane
#define TPB 256
#define NWARP 8
#define CH 128          // rows per chunk
#define RPW (CH / NWARP)
#define ROWSPLIT 16
#define NROWS (NN / ROWSPLIT)   // 512
#define NCHUNK (NROWS / CH)     // 4
#define NCB (MM / BC)   // 32 col blocks

typedef unsigned long long ull;

__device__ float g_rowpart[BB * NCB * NN];      // [b][colblock][row]
__device__ float g_colpart[BB * ROWSPLIT * MM]; // [b][split][col]

static __device__ __forceinline__ ull pk2(float lo, float hi) {
    ull r; asm("mov.b64 %0, {%1, %2};" : "=l"(r) : "f"(lo), "f"(hi)); return r;
}
static __device__ __forceinline__ void upk2(ull v, float& lo, float& hi) {
    asm("mov.b64 {%0, %1}, %2;" : "=f"(lo), "=f"(hi) : "l"(v));
}
static __device__ __forceinline__ ull ffma2(ull a, ull b, ull c) {
    ull d; asm("fma.rn.f32x2 %0, %1, %2, %3;" : "=l"(d) : "l"(a), "l"(b), "l"(c)); return d;
}
static __device__ __forceinline__ ull fadd2(ull a, ull b) {
    ull d; asm("add.rn.f32x2 %0, %1, %2;" : "=l"(d) : "l"(a), "l"(b)); return d;
}

__global__ void __launch_bounds__(TPB, 2)
chamfer_fused(const float* __restrict__ x1, const float* __restrict__ x2)
{
    __shared__ ulonglong2 RA[CH];     // (x,x),(y,y) per row
    __shared__ ulonglong2 RB[CH];     // (z,z),(s1,s1) per row
    __shared__ float4 colsm[BC];      // (-2x,-2y,-2z,s2) per col
    __shared__ float cand[CH][33];    // row-min candidates, padded stride

    const int tid  = threadIdx.x;
    const int lane = tid & 31;
    const int w    = tid >> 5;
    const int b     = blockIdx.z;
    const int split = blockIdx.y;
    const int colbase  = blockIdx.x * BC;
    const int rowbase0 = split * NROWS;

    // ---- prologue: load + preprocess the 256-col tile ----
    if (tid < BC) {
        const float* p = x2 + ((size_t)b * MM + colbase + tid) * 3;
        float x = p[0], y = p[1], z = p[2];
        colsm[tid] = make_float4(-2.0f * x, -2.0f * y, -2.0f * z,
                                 x * x + y * y + z * z);
    }
    __syncthreads();

    // Each lane caches its 4 colpairs in registers (every warp duplicates).
    ull cxx[NCP], cyy[NCP], czz[NCP], cww[NCP];
#pragma unroll
    for (int cp = 0; cp < NCP; cp++) {
        float4 a = colsm[lane * KC + 2 * cp];
        float4 c = colsm[lane * KC + 2 * cp + 1];
        cxx[cp] = pk2(a.x, c.x);
        cyy[cp] = pk2(a.y, c.y);
        czz[cp] = pk2(a.z, c.z);
        cww[cp] = pk2(a.w, c.w);
    }

    float colacc[KC];
#pragma unroll
    for (int j = 0; j < KC; j++) colacc[j] = 3.4e38f;

    // ---- prefetch chunk 0 rows into registers ----
    float prx = 0.f, pry = 0.f, prz = 0.f;
    if (tid < CH) {
        const float* p = x1 + ((size_t)b * NN + rowbase0 + tid) * 3;
        prx = p[0]; pry = p[1]; prz = p[2];
    }

    // ---- main loop: stream rows in 128-row chunks ----
    for (int ch = 0; ch < NCHUNK; ch++) {
        const int rowbase = rowbase0 + ch * CH;

        __syncthreads();   // previous chunk's cand/RA/RB readers are done
        if (tid < CH) {
            float s = prx * prx + pry * pry + prz * prz;
            RA[tid] = make_ulonglong2(pk2(prx, prx), pk2(pry, pry));
            RB[tid] = make_ulonglong2(pk2(prz, prz), pk2(s, s));
            if (ch + 1 < NCHUNK) {   // next chunk's loads in flight during
                const float* p =     // the 16-row compute below
                    x1 + ((size_t)b * NN + rowbase + CH + tid) * 3;
                prx = p[0]; pry = p[1]; prz = p[2];
            }
        }
        __syncthreads();

        // warp w handles rows [w*16, w*16+16) of this chunk
#pragma unroll
        for (int rr = 0; rr < RPW; rr++) {
            const int r = w * RPW + rr;
            const ulonglong2 ra = RA[r];   // LDS.128 broadcast
            const ulonglong2 rb = RB[r];
            float racc0 = 3.4e38f, racc1 = 3.4e38f;
#pragma unroll
            for (int cp = 0; cp < NCP; cp++) {
                // v = s2_j - 2*dot(i,j)    (row candidate, s1 folded out)
                ull v = ffma2(cxx[cp], ra.x,
                        ffma2(cyy[cp], ra.y,
                        ffma2(czz[cp], rb.x, cww[cp])));
                float vl, vh; upk2(v, vl, vh);
                racc0 = fminf(racc0, vl);
                racc1 = fminf(racc1, vh);
                // c = v + s1_i = full squared distance (col candidate)
                ull c = fadd2(v, rb.y);
                float cl, chh; upk2(c, cl, chh);
                colacc[2 * cp]     = fminf(colacc[2 * cp], cl);
                colacc[2 * cp + 1] = fminf(colacc[2 * cp + 1], chh);
            }
            cand[r][lane] = fminf(racc0, racc1);
        }
        __syncthreads();

        // chunk row-reduce: 2 threads per row, conflict-free by stride-33 pad
        {
            const int r = tid >> 1;
            const int h = tid & 1;
            float m = cand[r][h * 16 + 0];
#pragma unroll
            for (int i = 1; i < 16; i++)
                m = fminf(m, cand[r][h * 16 + i]);
            m = fminf(m, __shfl_xor_sync(0xFFFFFFFFu, m, 1));
            if (h == 0)
                g_rowpart[((size_t)b * NCB + blockIdx.x) * NN + rowbase + r] = m;
        }
    }

    // ---- epilogue: reduce colacc across the 8 warps (reuse cand as scratch) ----
    float* colred = &cand[0][0];   // needs 8*256 floats <= 128*33
    __syncthreads();
#pragma unroll
    for (int j = 0; j < KC; j++)
        colred[w * BC + lane * KC + j] = colacc[j];
    __syncthreads();
    {
        float m = colred[tid];
#pragma unroll
        for (int ww = 1; ww < NWARP; ww++)
            m = fminf(m, colred[ww * BC + tid]);
        g_colpart[((size_t)b * ROWSPLIT + split) * MM + colbase + tid] = m;
    }
}

// out[0..B*N) = d1 = min over colblocks of rowpart + s1
// out[B*N..)  = d2 = min over splits of colpart
__global__ void final_kernel(const float* __restrict__ x1, float* __restrict__ out)
{
    const int i = blockIdx.x * blockDim.x + threadIdx.x;
    if (i < BB * NN) {
        const int b = i / NN, row = i % NN;
        float m = 3.4e38f;
#pragma unroll
        for (int cb = 0; cb < NCB; cb++)
            m = fminf(m, g_rowpart[((size_t)b * NCB + cb) * NN + row]);
        const float* p = x1 + (size_t)i * 3;
        out[i] = m + p[0] * p[0] + p[1] * p[1] + p[2] * p[2];
    } else if (i < BB * NN + BB * MM) {
        const int j = i - BB * NN;
        const int b = j / MM, col = j % MM;
        float m = 3.4e38f;
#pragma unroll
        for (int sp = 0; sp < ROWSPLIT; sp++)
            m = fminf(m, g_colpart[((size_t)b * ROWSPLIT + sp) * MM + col]);
        out[i] = m;
    }
}

extern "C" void kernel_launch(void* const* d_in, const int* in_sizes, int n_in,
                              void* d_out, int out_size)
{
    const float* xyz1 = (const float*)d_in[0];   // [B, N, 3]
    const float* xyz2 = (const float*)d_in[1];   // [B, M, 3]
    float* out = (float*)d_out;

    dim3 grid(NCB, ROWSPLIT, BB);   // (32, 16, 4) = 2048 blocks
    chamfer_fused<<<grid, TPB>>>(xyz1, xyz2);

    const int total = BB * NN + BB * MM;
    final_kernel<<<(total + TPB - 1) / TPB, TPB>>>(xyz1, out);
}

// round 7
// speedup vs baseline: 1.0539x; 1.0539x over previous
#include <cuda_runtime.h>

// ChamferDistance_755914244601: B=4, N=M=8192, 3D points.
// Fused single pass; packed f32x2 FFMA2/FADD2 distance chain, scalar FMNMX
// mins. Block-level results go straight into d_out via uint atomicMin on
// raw float bits (valid: candidates are non-negative full distances).

#define BB 4
#define NN 8192
#define MM 8192
#define BC 256          // cols per block
#define KC 8            // cols per lane
#define NCP (KC / 2)    // colpairs per lane
#define TPB 256
#define NWARP 8
#define CH 128          // rows per chunk
#define RPW (CH / NWARP)
#define ROWSPLIT 16
#define NROWS (NN / ROWSPLIT)   // 512
#define NCHUNK (NROWS / CH)     // 4
#define NCB (MM / BC)   // 32 col blocks

typedef unsigned long long ull;

static __device__ __forceinline__ ull pk2(float lo, float hi) {
    ull r; asm("mov.b64 %0, {%1, %2};" : "=l"(r) : "f"(lo), "f"(hi)); return r;
}
static __device__ __forceinline__ void upk2(ull v, float& lo, float& hi) {
    asm("mov.b64 {%0, %1}, %2;" : "=f"(lo), "=f"(hi) : "l"(v));
}
static __device__ __forceinline__ ull ffma2(ull a, ull b, ull c) {
    ull d; asm("fma.rn.f32x2 %0, %1, %2, %3;" : "=l"(d) : "l"(a), "l"(b), "l"(c)); return d;
}
static __device__ __forceinline__ ull fadd2(ull a, ull b) {
    ull d; asm("add.rn.f32x2 %0, %1, %2;" : "=l"(d) : "l"(a), "l"(b)); return d;
}

// Seed d_out (B*N + B*M floats) with FLT_MAX bit pattern.
__global__ void init_kernel(unsigned int* __restrict__ out)
{
    const int i = blockIdx.x * blockDim.x + threadIdx.x;
    if (i < BB * NN + BB * MM) out[i] = 0x7F7FFFFFu;   // FLT_MAX
}

__global__ void __launch_bounds__(TPB, 3)
chamfer_fused(const float* __restrict__ x1, const float* __restrict__ x2,
              unsigned int* __restrict__ out)
{
    __shared__ ulonglong2 RA[CH];     // (x,x),(y,y) per row
    __shared__ ulonglong2 RB[CH];     // (z,z),(s1,s1) per row
    __shared__ float4 colsm[BC];      // (-2x,-2y,-2z,s2) per col
    __shared__ float cand[CH][33];    // row-min candidates, padded stride

    const int tid  = threadIdx.x;
    const int lane = tid & 31;
    const int w    = tid >> 5;
    const int b     = blockIdx.z;
    const int split = blockIdx.y;
    const int colbase  = blockIdx.x * BC;
    const int rowbase0 = split * NROWS;

    // ---- prologue: load + preprocess the 256-col tile ----
    if (tid < BC) {
        const float* p = x2 + ((size_t)b * MM + colbase + tid) * 3;
        float x = p[0], y = p[1], z = p[2];
        colsm[tid] = make_float4(-2.0f * x, -2.0f * y, -2.0f * z,
                                 x * x + y * y + z * z);
    }
    __syncthreads();

    // Each lane caches its 4 colpairs in registers (every warp duplicates).
    ull cxx[NCP], cyy[NCP], czz[NCP], cww[NCP];
#pragma unroll
    for (int cp = 0; cp < NCP; cp++) {
        float4 a = colsm[lane * KC + 2 * cp];
        float4 c = colsm[lane * KC + 2 * cp + 1];
        cxx[cp] = pk2(a.x, c.x);
        cyy[cp] = pk2(a.y, c.y);
        czz[cp] = pk2(a.z, c.z);
        cww[cp] = pk2(a.w, c.w);
    }

    float colacc[KC];
#pragma unroll
    for (int j = 0; j < KC; j++) colacc[j] = 3.4e38f;

    // ---- prefetch chunk 0 rows into registers ----
    float prx = 0.f, pry = 0.f, prz = 0.f;
    if (tid < CH) {
        const float* p = x1 + ((size_t)b * NN + rowbase0 + tid) * 3;
        prx = p[0]; pry = p[1]; prz = p[2];
    }

    // ---- main loop: stream rows in 128-row chunks ----
    for (int ch = 0; ch < NCHUNK; ch++) {
        const int rowbase = rowbase0 + ch * CH;

        __syncthreads();   // previous chunk's cand/RA/RB readers are done
        if (tid < CH) {
            float s = prx * prx + pry * pry + prz * prz;
            RA[tid] = make_ulonglong2(pk2(prx, prx), pk2(pry, pry));
            RB[tid] = make_ulonglong2(pk2(prz, prz), pk2(s, s));
            if (ch + 1 < NCHUNK) {   // next chunk's loads fly during compute
                const float* p =
                    x1 + ((size_t)b * NN + rowbase + CH + tid) * 3;
                prx = p[0]; pry = p[1]; prz = p[2];
            }
        }
        __syncthreads();

        // warp w handles rows [w*16, w*16+16) of this chunk
#pragma unroll
        for (int rr = 0; rr < RPW; rr++) {
            const int r = w * RPW + rr;
            const ulonglong2 ra = RA[r];   // LDS.128 broadcast
            const ulonglong2 rb = RB[r];
            float racc0 = 3.4e38f, racc1 = 3.4e38f;
#pragma unroll
            for (int cp = 0; cp < NCP; cp++) {
                // v = s2_j - 2*dot(i,j)    (row candidate, s1 folded out)
                ull v = ffma2(cxx[cp], ra.x,
                        ffma2(cyy[cp], ra.y,
                        ffma2(czz[cp], rb.x, cww[cp])));
                float vl, vh; upk2(v, vl, vh);
                racc0 = fminf(racc0, vl);
                racc1 = fminf(racc1, vh);
                // c = v + s1_i = full squared distance (col candidate)
                ull c = fadd2(v, rb.y);
                float cl, chh; upk2(c, cl, chh);
                colacc[2 * cp]     = fminf(colacc[2 * cp], cl);
                colacc[2 * cp + 1] = fminf(colacc[2 * cp + 1], chh);
            }
            cand[r][lane] = fminf(racc0, racc1);
        }
        __syncthreads();

        // chunk row-reduce: 2 threads per row, conflict-free by stride-33 pad
        {
            const int r = tid >> 1;
            const int h = tid & 1;
            float m = cand[r][h * 16 + 0];
#pragma unroll
            for (int i = 1; i < 16; i++)
                m = fminf(m, cand[r][h * 16 + i]);
            m = fminf(m, __shfl_xor_sync(0xFFFFFFFFu, m, 1));
            if (h == 0) {
                float s1r;                 // s1 of row r (lo half of RB[r].y)
                {
                    float a_, b_; upk2(RB[r].y, a_, b_);
                    s1r = a_;
                }
                // full distance = v_min + s1; non-negative -> uint atomicMin
                atomicMin(&out[(size_t)b * NN + rowbase + r],
                          __float_as_uint(m + s1r));
            }
        }
    }

    // ---- epilogue: reduce colacc across the 8 warps (reuse cand as scratch) ----
    float* colred = &cand[0][0];   // needs 8*256 floats <= 128*33
    __syncthreads();
#pragma unroll
    for (int j = 0; j < KC; j++)
        colred[w * BC + lane * KC + j] = colacc[j];
    __syncthreads();
    {
        float m = colred[tid];
#pragma unroll
        for (int ww = 1; ww < NWARP; ww++)
            m = fminf(m, colred[ww * BC + tid]);
        atomicMin(&out[(size_t)(BB * NN) + (size_t)b * MM + colbase + tid],
                  __float_as_uint(m));
    }
}

extern "C" void kernel_launch(void* const* d_in, const int* in_sizes, int n_in,
                              void* d_out, int out_size)
{
    const float* xyz1 = (const float*)d_in[0];   // [B, N, 3]
    const float* xyz2 = (const float*)d_in[1];   // [B, M, 3]
    unsigned int* out = (unsigned int*)d_out;

    const int total = BB * NN + BB * MM;
    init_kernel<<<(total + TPB - 1) / TPB, TPB>>>(out);

    dim3 grid(NCB, ROWSPLIT, BB);   // (32, 16, 4) = 2048 blocks
    chamfer_fused<<<grid, TPB>>>(xyz1, xyz2, out);
}